// round 1
// baseline (speedup 1.0000x reference)
#include <cuda_runtime.h>
#include <math.h>

// GPT-2 small, 4 layers: B=2, S=1024, E=768, H=12, D=64, V=50257
#define B_   2
#define S_   1024
#define E_   768
#define H_   12
#define D_   64
#define L_   4
#define V_   50257
#define M_   (B_ * S_)      // 2048 token rows
#define E3_  (3 * E_)       // 2304
#define E4_  (4 * E_)       // 3072
#define BH_  (B_ * H_)      // 24

// ---------------- scratch (allocation-free: device globals) ----------------
__device__ float g_x[M_ * E_];                         // residual stream
__device__ float g_h[M_ * E_];                         // layernorm output
__device__ float g_qkv[M_ * E3_];                      // qkv projections
__device__ float g_scores[(size_t)BH_ * S_ * S_];      // attention scores/probs (~100MB)
__device__ float g_o[M_ * E_];                         // attention output
__device__ float g_fc[M_ * E4_];                       // MLP hidden

// ---------------- reductions ----------------
__device__ __forceinline__ float wsum(float v) {
#pragma unroll
    for (int o = 16; o; o >>= 1) v += __shfl_xor_sync(0xffffffffu, v, o);
    return v;
}
__device__ __forceinline__ float wmax(float v) {
#pragma unroll
    for (int o = 16; o; o >>= 1) v = fmaxf(v, __shfl_xor_sync(0xffffffffu, v, o));
    return v;
}

// block reduce over 256 threads (8 warps). Leading sync protects shared reuse.
__device__ __forceinline__ float blockSum(float v, float* red, float* stat, int tid) {
    __syncthreads();
    v = wsum(v);
    if ((tid & 31) == 0) red[tid >> 5] = v;
    __syncthreads();
    if (tid < 32) {
        float t = (tid < 8) ? red[tid] : 0.f;
#pragma unroll
        for (int o = 4; o; o >>= 1) t += __shfl_xor_sync(0xffffffffu, t, o);
        if (tid == 0) *stat = t;
    }
    __syncthreads();
    return *stat;
}
__device__ __forceinline__ float blockMax(float v, float* red, float* stat, int tid) {
    __syncthreads();
    v = wmax(v);
    if ((tid & 31) == 0) red[tid >> 5] = v;
    __syncthreads();
    if (tid < 32) {
        float t = (tid < 8) ? red[tid] : -3.4e38f;
#pragma unroll
        for (int o = 4; o; o >>= 1) t = fmaxf(t, __shfl_xor_sync(0xffffffffu, t, o));
        if (tid == 0) *stat = t;
    }
    __syncthreads();
    return *stat;
}

// ---------------- embedding: x = wte[ids] + wpe[pos] ----------------
__global__ __launch_bounds__(256) void k_embed(const int* __restrict__ ids,
                                               const float* __restrict__ wte,
                                               const float* __restrict__ wpe,
                                               float* __restrict__ x) {
    int row = blockIdx.x;
    int s   = row & (S_ - 1);
    int id  = ids[row];
    const float* te = wte + (size_t)id * E_;
    const float* pe = wpe + (size_t)s * E_;
    float* xr = x + (size_t)row * E_;
    for (int e = threadIdx.x; e < E_; e += 256) xr[e] = te[e] + pe[e];
}

// ---------------- layernorm over 768, one block per row ----------------
__global__ __launch_bounds__(256) void k_ln(const float* __restrict__ x,
                                            const float* __restrict__ gamma,
                                            const float* __restrict__ beta,
                                            float* __restrict__ out) {
    __shared__ float red[8];
    __shared__ float stat;
    int row = blockIdx.x, tid = threadIdx.x;
    const float* xr = x + (size_t)row * E_;
    float v0 = xr[tid], v1 = xr[tid + 256], v2 = xr[tid + 512];
    float mu = blockSum(v0 + v1 + v2, red, &stat, tid) * (1.0f / E_);
    float d0 = v0 - mu, d1 = v1 - mu, d2 = v2 - mu;
    float var = blockSum(d0 * d0 + d1 * d1 + d2 * d2, red, &stat, tid) * (1.0f / E_);
    float rstd = rsqrtf(var + 1e-6f);
    float* orow = out + (size_t)row * E_;
    orow[tid]       = d0 * rstd * gamma[tid]       + beta[tid];
    orow[tid + 256] = d1 * rstd * gamma[tid + 256] + beta[tid + 256];
    orow[tid + 512] = d2 * rstd * gamma[tid + 512] + beta[tid + 512];
}

// ---------------- tiled SGEMM: C = A[M,K] @ B[K,N] (+bias)(gelu)(+res) ------
// 128x128 block tile, BK=8, 256 threads, 8x8 register tile per thread.
template <bool BIAS, bool GELU_T, bool RES>
__global__ __launch_bounds__(256) void k_sgemm(const float* __restrict__ A,
                                               const float* __restrict__ Bm,
                                               const float* __restrict__ bias,
                                               const float* __restrict__ res,
                                               float* __restrict__ C,
                                               int M, int N, int K) {
    __shared__ float As[8][128];
    __shared__ float Bs[8][128];
    int tid = threadIdx.x;
    int m0 = blockIdx.y << 7;
    int n0 = blockIdx.x << 7;

    int aRow = tid >> 1;            // 0..127
    int aCol = (tid & 1) << 2;      // 0 or 4
    int bRow = tid >> 5;            // 0..7
    int bCol = (tid & 31) << 2;     // 0..124
    int tr = (tid >> 4) << 3;       // 0..120 step 8
    int tc = (tid & 15) << 3;       // 0..120 step 8

    float acc[8][8];
#pragma unroll
    for (int i = 0; i < 8; i++)
#pragma unroll
        for (int j = 0; j < 8; j++) acc[i][j] = 0.f;

    const float* Ap = A + (size_t)(m0 + aRow) * K + aCol;   // M%128==0, K%8==0 guaranteed
    const float* Bp = Bm + (size_t)bRow * N + n0 + bCol;
    int nb = n0 + bCol;

    for (int k0 = 0; k0 < K; k0 += 8) {
        float4 av = *(const float4*)Ap;       // K%4==0, 16B aligned
        As[aCol + 0][aRow] = av.x;
        As[aCol + 1][aRow] = av.y;
        As[aCol + 2][aRow] = av.z;
        As[aCol + 3][aRow] = av.w;
#pragma unroll
        for (int j = 0; j < 4; j++)
            Bs[bRow][bCol + j] = (nb + j < N) ? Bp[j] : 0.f;
        __syncthreads();

#pragma unroll
        for (int k = 0; k < 8; k++) {
            float4 a0 = *(const float4*)&As[k][tr];
            float4 a1 = *(const float4*)&As[k][tr + 4];
            float4 b0 = *(const float4*)&Bs[k][tc];
            float4 b1 = *(const float4*)&Bs[k][tc + 4];
            float ra[8] = {a0.x, a0.y, a0.z, a0.w, a1.x, a1.y, a1.z, a1.w};
            float rb[8] = {b0.x, b0.y, b0.z, b0.w, b1.x, b1.y, b1.z, b1.w};
#pragma unroll
            for (int i = 0; i < 8; i++)
#pragma unroll
                for (int j = 0; j < 8; j++)
                    acc[i][j] = fmaf(ra[i], rb[j], acc[i][j]);
        }
        __syncthreads();
        Ap += 8;
        Bp += (size_t)8 * N;
    }

#pragma unroll
    for (int i = 0; i < 8; i++) {
        int m = m0 + tr + i;
#pragma unroll
        for (int j = 0; j < 8; j++) {
            int n = n0 + tc + j;
            if (n < N) {
                float t = acc[i][j];
                if (BIAS) t += bias[n];
                if (GELU_T) {
                    float u = t;
                    float c = 0.7978845608028654f * (u + 0.044715f * u * u * u);
                    t = 0.5f * u * (1.0f + tanhf(c));
                }
                size_t idx = (size_t)m * N + n;
                if (RES) t += res[idx];
                C[idx] = t;
            }
        }
    }
}

// ---------------- attention scores: 64x64 tile per block ----------------
// scores[b,h,q,k] = (q.k)/8 if k<=q else -10000
__global__ __launch_bounds__(256) void k_scores(const float* __restrict__ qkv,
                                                float* __restrict__ sc) {
    int bh = blockIdx.z;
    int b = bh / H_, h = bh % H_;
    int q0 = blockIdx.y << 6;
    int k0 = blockIdx.x << 6;
    int tid = threadIdx.x;
    int tr = tid >> 4, tc = tid & 15;

    float* srow = sc + ((size_t)bh * S_) * S_;

    if (k0 > q0 + 63) {  // fully masked tile
#pragma unroll
        for (int i = 0; i < 4; i++) {
            int q = q0 + tr * 4 + i;
            float4 mv = make_float4(-10000.f, -10000.f, -10000.f, -10000.f);
            *(float4*)&srow[(size_t)q * S_ + k0 + tc * 4] = mv;
        }
        return;
    }

    __shared__ float Qs[64][65];
    __shared__ float Ks[64][65];
    for (int i = tid; i < 64 * 64; i += 256) {
        int r = i >> 6, c = i & 63;
        Qs[r][c] = qkv[(size_t)(b * S_ + q0 + r) * E3_ + h * D_ + c];
        Ks[r][c] = qkv[(size_t)(b * S_ + k0 + r) * E3_ + E_ + h * D_ + c];
    }
    __syncthreads();

    float acc[4][4];
#pragma unroll
    for (int i = 0; i < 4; i++)
#pragma unroll
        for (int j = 0; j < 4; j++) acc[i][j] = 0.f;

#pragma unroll 4
    for (int d = 0; d < 64; d++) {
        float ra[4], rb[4];
#pragma unroll
        for (int i = 0; i < 4; i++) ra[i] = Qs[tr * 4 + i][d];
#pragma unroll
        for (int j = 0; j < 4; j++) rb[j] = Ks[tc * 4 + j][d];
#pragma unroll
        for (int i = 0; i < 4; i++)
#pragma unroll
            for (int j = 0; j < 4; j++) acc[i][j] = fmaf(ra[i], rb[j], acc[i][j]);
    }

#pragma unroll
    for (int i = 0; i < 4; i++) {
        int q = q0 + tr * 4 + i;
        float4 v;
        float* vp = &v.x;
#pragma unroll
        for (int j = 0; j < 4; j++) {
            int k = k0 + tc * 4 + j;
            vp[j] = (k <= q) ? acc[i][j] * 0.125f : -10000.f;
        }
        *(float4*)&srow[(size_t)q * S_ + k0 + tc * 4] = v;
    }
}

// ---------------- row softmax over 1024 ----------------
__global__ __launch_bounds__(256) void k_softmax(float* __restrict__ sc) {
    __shared__ float red[8];
    __shared__ float stat;
    int tid = threadIdx.x;
    float* p = sc + (size_t)blockIdx.x * S_;
    float v0 = p[tid], v1 = p[tid + 256], v2 = p[tid + 512], v3 = p[tid + 768];
    float m = blockMax(fmaxf(fmaxf(v0, v1), fmaxf(v2, v3)), red, &stat, tid);
    float e0 = __expf(v0 - m), e1 = __expf(v1 - m), e2 = __expf(v2 - m), e3 = __expf(v3 - m);
    float s = blockSum(e0 + e1 + e2 + e3, red, &stat, tid);
    float inv = 1.0f / s;
    p[tid] = e0 * inv; p[tid + 256] = e1 * inv; p[tid + 512] = e2 * inv; p[tid + 768] = e3 * inv;
}

// ---------------- attn @ V: 64 q-rows x 64 d per block ----------------
__global__ __launch_bounds__(256) void k_av(const float* __restrict__ sc,
                                            const float* __restrict__ qkv,
                                            float* __restrict__ o) {
    int bh = blockIdx.y;
    int b = bh / H_, h = bh % H_;
    int q0 = blockIdx.x << 6;
    int tid = threadIdx.x;
    int tr = tid >> 4, tc = tid & 15;

    __shared__ float Ps[64][65];
    __shared__ float Vs[64][65];

    float acc[4][4];
#pragma unroll
    for (int i = 0; i < 4; i++)
#pragma unroll
        for (int j = 0; j < 4; j++) acc[i][j] = 0.f;

    int nkt = blockIdx.x + 1;  // causal: probs are exactly 0 beyond q
    for (int kt = 0; kt < nkt; kt++) {
        for (int i = tid; i < 64 * 64; i += 256) {
            int r = i >> 6, c = i & 63;
            Ps[r][c] = sc[((size_t)bh * S_ + q0 + r) * S_ + kt * 64 + c];
            Vs[r][c] = qkv[(size_t)(b * S_ + kt * 64 + r) * E3_ + 2 * E_ + h * D_ + c];
        }
        __syncthreads();
#pragma unroll 4
        for (int k = 0; k < 64; k++) {
            float ra[4], rb[4];
#pragma unroll
            for (int i = 0; i < 4; i++) ra[i] = Ps[tr * 4 + i][k];
#pragma unroll
            for (int j = 0; j < 4; j++) rb[j] = Vs[k][tc * 4 + j];
#pragma unroll
            for (int i = 0; i < 4; i++)
#pragma unroll
                for (int j = 0; j < 4; j++) acc[i][j] = fmaf(ra[i], rb[j], acc[i][j]);
        }
        __syncthreads();
    }

#pragma unroll
    for (int i = 0; i < 4; i++) {
        int q = q0 + tr * 4 + i;
        float4 v = make_float4(acc[i][0], acc[i][1], acc[i][2], acc[i][3]);
        *(float4*)&o[(size_t)(b * S_ + q) * E_ + h * D_ + tc * 4] = v;
    }
}

// ---------------- launcher ----------------
extern "C" void kernel_launch(void* const* d_in, const int* in_sizes, int n_in,
                              void* d_out, int out_size) {
    (void)in_sizes; (void)n_in; (void)out_size;
    const int*   ids  = (const int*)  d_in[0];
    const float* wte  = (const float*)d_in[1];
    const float* wpe  = (const float*)d_in[2];
    const float* ln1s = (const float*)d_in[3];
    const float* ln1b = (const float*)d_in[4];
    const float* wqkv = (const float*)d_in[5];
    const float* bqkv = (const float*)d_in[6];
    const float* wao  = (const float*)d_in[7];
    const float* bao  = (const float*)d_in[8];
    const float* ln2s = (const float*)d_in[9];
    const float* ln2b = (const float*)d_in[10];
    const float* wfc  = (const float*)d_in[11];
    const float* bfc  = (const float*)d_in[12];
    const float* wmp  = (const float*)d_in[13];
    const float* bmp  = (const float*)d_in[14];
    const float* lnfs = (const float*)d_in[15];
    const float* lnfb = (const float*)d_in[16];
    const float* wlm  = (const float*)d_in[17];
    float* out = (float*)d_out;

    float *x, *h, *qkv, *sc, *o, *fc;
    cudaGetSymbolAddress((void**)&x,   g_x);
    cudaGetSymbolAddress((void**)&h,   g_h);
    cudaGetSymbolAddress((void**)&qkv, g_qkv);
    cudaGetSymbolAddress((void**)&sc,  g_scores);
    cudaGetSymbolAddress((void**)&o,   g_o);
    cudaGetSymbolAddress((void**)&fc,  g_fc);

    k_embed<<<M_, 256>>>(ids, wte, wpe, x);

    for (int l = 0; l < L_; l++) {
        // --- attention ---
        k_ln<<<M_, 256>>>(x, ln1s + l * E_, ln1b + l * E_, h);
        k_sgemm<true, false, false><<<dim3(E3_ / 128, M_ / 128), 256>>>(
            h, wqkv + (size_t)l * E_ * E3_, bqkv + l * E3_, nullptr, qkv, M_, E3_, E_);
        k_scores<<<dim3(S_ / 64, S_ / 64, BH_), 256>>>(qkv, sc);
        k_softmax<<<BH_ * S_, 256>>>(sc);
        k_av<<<dim3(S_ / 64, BH_), 256>>>(sc, qkv, o);
        k_sgemm<true, false, true><<<dim3(E_ / 128, M_ / 128), 256>>>(
            o, wao + (size_t)l * E_ * E_, bao + l * E_, x, x, M_, E_, E_);
        // --- MLP ---
        k_ln<<<M_, 256>>>(x, ln2s + l * E_, ln2b + l * E_, h);
        k_sgemm<true, true, false><<<dim3(E4_ / 128, M_ / 128), 256>>>(
            h, wfc + (size_t)l * E_ * E4_, bfc + l * E4_, nullptr, fc, M_, E4_, E_);
        k_sgemm<true, false, true><<<dim3(E_ / 128, M_ / 128), 256>>>(
            fc, wmp + (size_t)l * E4_ * E_, bmp + l * E_, x, x, M_, E_, E4_);
    }

    // --- final LN + LM head ---
    k_ln<<<M_, 256>>>(x, lnfs, lnfb, h);
    k_sgemm<false, false, false><<<dim3((V_ + 127) / 128, M_ / 128), 256>>>(
        h, wlm, nullptr, nullptr, out, M_, V_, E_);
}